// round 16
// baseline (speedup 1.0000x reference)
#include <cuda_runtime.h>
#include <cuda_fp16.h>
#include <cstdint>

#define BATCH 16384
#define CODE  512
#define HID   1024
#define NCHAIN 4
#define CROWS (BATCH / NCHAIN)        // 4096 rows per chain

// ---------------- static device scratch ----------------
__device__ __half g_W[CODE*HID + 6*CODE*CODE];
__device__ __half g_V[3][BATCH*CODE];    // 3-buffer rotation (no WAR race)

// ---------------- helpers ----------------
__device__ __forceinline__ uint32_t smem_u32(const void* p) {
    uint32_t a;
    asm("{ .reg .u64 t; cvta.to.shared.u64 t, %1; cvt.u32.u64 %0, t; }" : "=r"(a) : "l"(p));
    return a;
}
__device__ __forceinline__ void ldsm4(uint32_t* r, uint32_t a) {
    asm volatile("ldmatrix.sync.aligned.m8n8.x4.shared.b16 {%0,%1,%2,%3}, [%4];"
        : "=r"(r[0]), "=r"(r[1]), "=r"(r[2]), "=r"(r[3]) : "r"(a));
}
__device__ __forceinline__ void mma16816(float* d, const uint32_t* a, uint32_t b0, uint32_t b1) {
    asm volatile("mma.sync.aligned.m16n8k16.row.col.f32.f16.f16.f32 "
        "{%0,%1,%2,%3},{%4,%5,%6,%7},{%8,%9},{%0,%1,%2,%3};"
        : "+f"(d[0]), "+f"(d[1]), "+f"(d[2]), "+f"(d[3])
        : "r"(a[0]), "r"(a[1]), "r"(a[2]), "r"(a[3]), "r"(b0), "r"(b1));
}
#define CP_ASYNC(s, g) asm volatile("cp.async.cg.shared.global [%0], [%1], 16;" :: "r"(s), "l"(g))
#define CP_COMMIT()    asm volatile("cp.async.commit_group;")
#define CP_WAIT1()     asm volatile("cp.async.wait_group 1;")

__device__ __forceinline__ uint32_t pack_h2(float a, float b) {
    __half2 h = __halves2half2(__float2half_rn(a), __float2half_rn(b));
    return *(uint32_t*)&h;
}

// ---------------- converter: fp32 -> fp16 (weights only now) ----------------
__global__ void cvt_h(const float4* __restrict__ src, __half2* __restrict__ w, int n4) {
    int i = blockIdx.x * blockDim.x + threadIdx.x;
    if (i >= n4) return;
    float4 v = src[i];
    w[2*i]   = __halves2half2(__float2half_rn(v.x), __float2half_rn(v.y));
    w[2*i+1] = __halves2half2(__float2half_rn(v.z), __float2half_rn(v.w));
}

#define SEC_B    16384
#define STAGE_B  (2 * SEC_B)           // 32768
#define GSMEM    (3 * STAGE_B)         // 98304

// ---------------- layer 1..6 GEMM (R13 winner, unchanged) ----------------
template<int K>
__global__ void __launch_bounds__(256, 2)
gemm_layer(const __half* __restrict__ A, const __half* __restrict__ W,
           const float* __restrict__ bias, __half* __restrict__ Vout)
{
    extern __shared__ char sm[];
    const uint32_t sb = smem_u32(sm);
    const int tid = threadIdx.x, lane = tid & 31, wid = tid >> 5;
    const int wm = wid & 1, wn = wid >> 1;
    const int m0 = blockIdx.x * 128, n0 = blockIdx.y * 128;
    constexpr int NITER = K / 64;

    const int lrow = tid >> 3, lc = tid & 7;
    uint32_t sOff[4], gAo[4], gBo[4];
    #pragma unroll
    for (int q = 0; q < 4; q++) {
        int row = lrow + q * 32;
        sOff[q] = (uint32_t)row * 128 + (uint32_t)((lc ^ (row & 7)) << 4);
        gAo[q] = (uint32_t)(m0 + row) * (K * 2) + lc * 16;
        gBo[q] = (uint32_t)(n0 + row) * (K * 2) + lc * 16;
    }

    int rA[4];
    #pragma unroll
    for (int mt = 0; mt < 4; mt++) rA[mt] = wm * 64 + mt * 16 + (lane & 15);
    const int cA = lane >> 4;
    int nB[2];
    #pragma unroll
    for (int p = 0; p < 2; p++) nB[p] = wn * 32 + p * 16 + (lane & 7) + ((lane >> 4) << 3);
    const int cB = (lane >> 3) & 1;

    const int gid = lane >> 2, qid = lane & 3;
    float bcol[8];
    #pragma unroll
    for (int nt = 0; nt < 4; nt++) {
        const int col = n0 + wn * 32 + nt * 8 + qid * 2;
        bcol[nt * 2]     = __ldg(bias + col);
        bcol[nt * 2 + 1] = __ldg(bias + col + 1);
    }

    float acc[16][4] = {};

    auto prefetch = [&](int it) {
        if (it < NITER) {
            const uint32_t slot = sb + (uint32_t)(it % 3) * STAGE_B;
            const uint32_t koff = (uint32_t)it * 128;
            #pragma unroll
            for (int q = 0; q < 4; q++) {
                CP_ASYNC(slot + sOff[q],         (const char*)A + gAo[q] + koff);
                CP_ASYNC(slot + SEC_B + sOff[q], (const char*)W + gBo[q] + koff);
            }
        }
        CP_COMMIT();
    };

    prefetch(0);
    prefetch(1);

    #pragma unroll 1
    for (int it = 0; it < NITER; it++) {
        CP_WAIT1();
        __syncthreads();
        prefetch(it + 2);

        const uint32_t slot = sb + (uint32_t)(it % 3) * STAGE_B;
        #pragma unroll
        for (int ks = 0; ks < 4; ks++) {
            uint32_t a[4][4], w[2][4];
            #pragma unroll
            for (int mt = 0; mt < 4; mt++) {
                const uint32_t ro = (uint32_t)rA[mt] * 128 +
                    (uint32_t)((((ks * 2 + cA) ^ (rA[mt] & 7))) << 4);
                ldsm4(a[mt], slot + ro);
            }
            #pragma unroll
            for (int p = 0; p < 2; p++) {
                const uint32_t ro = (uint32_t)nB[p] * 128 +
                    (uint32_t)((((ks * 2 + cB) ^ (nB[p] & 7))) << 4);
                ldsm4(w[p], slot + SEC_B + ro);
            }
            #pragma unroll
            for (int mt = 0; mt < 4; mt++) {
                #pragma unroll
                for (int nt = 0; nt < 4; nt++) {
                    mma16816(acc[mt * 4 + nt], a[mt],
                             w[nt >> 1][(nt & 1) * 2], w[nt >> 1][(nt & 1) * 2 + 1]);
                }
            }
        }
    }

    #pragma unroll
    for (int mt = 0; mt < 4; mt++) {
        #pragma unroll
        for (int nt = 0; nt < 4; nt++) {
            const float* d = acc[mt * 4 + nt];
            const int row = m0 + wm * 64 + mt * 16 + gid;
            const int col = n0 + wn * 32 + nt * 8 + qid * 2;
            const float b0 = bcol[nt * 2], b1 = bcol[nt * 2 + 1];
            *(__half2*)(Vout + (size_t)row * CODE + col) =
                __halves2half2(__float2half_rn(d[0] + b0), __float2half_rn(d[1] + b1));
            *(__half2*)(Vout + (size_t)(row + 8) * CODE + col) =
                __halves2half2(__float2half_rn(d[2] + b0), __float2half_rn(d[3] + b1));
        }
    }
}

// ---------------- layer-0 GEMM with fused fp32->fp16 A conversion ----------------
// A is read as fp32 (LDG.128 into regs, 2-stage distance), converted and STS'd
// into the same swizzled fp16 layout at consume time. W path unchanged (cp.async).
__global__ void __launch_bounds__(256, 1)
gemm_l0(const float* __restrict__ A32, const __half* __restrict__ W,
        const float* __restrict__ bias, __half* __restrict__ Vout)
{
    constexpr int K = HID;
    constexpr int NITER = K / 64;      // 16
    extern __shared__ char sm[];
    const uint32_t sb = smem_u32(sm);
    const int tid = threadIdx.x, lane = tid & 31, wid = tid >> 5;
    const int wm = wid & 1, wn = wid >> 1;
    const int m0 = blockIdx.x * 128, n0 = blockIdx.y * 128;

    const int lrow = tid >> 3, lc = tid & 7;
    uint32_t sOff[4], gBo[4];
    size_t gAo32[4];
    #pragma unroll
    for (int q = 0; q < 4; q++) {
        int row = lrow + q * 32;
        sOff[q] = (uint32_t)row * 128 + (uint32_t)((lc ^ (row & 7)) << 4);
        gAo32[q] = (size_t)(m0 + row) * (K * 4) + lc * 32;   // fp32 bytes
        gBo[q]   = (uint32_t)(n0 + row) * (K * 2) + lc * 16;
    }

    int rA[4];
    #pragma unroll
    for (int mt = 0; mt < 4; mt++) rA[mt] = wm * 64 + mt * 16 + (lane & 15);
    const int cA = lane >> 4;
    int nB[2];
    #pragma unroll
    for (int p = 0; p < 2; p++) nB[p] = wn * 32 + p * 16 + (lane & 7) + ((lane >> 4) << 3);
    const int cB = (lane >> 3) & 1;

    const int gid = lane >> 2, qid = lane & 3;
    float bcol[8];
    #pragma unroll
    for (int nt = 0; nt < 4; nt++) {
        const int col = n0 + wn * 32 + nt * 8 + qid * 2;
        bcol[nt * 2]     = __ldg(bias + col);
        bcol[nt * 2 + 1] = __ldg(bias + col + 1);
    }

    float acc[16][4] = {};
    float4 aReg[2][4][2];                 // [stage-parity][q][2x float4]

    auto prefetch = [&](int it) {
        if (it < NITER) {
            const uint32_t slot = sb + (uint32_t)(it % 3) * STAGE_B;
            const uint32_t koff   = (uint32_t)it * 128;   // fp16 bytes (W)
            const uint32_t koff32 = (uint32_t)it * 256;   // fp32 bytes (A)
            const int b = it & 1;
            #pragma unroll
            for (int q = 0; q < 4; q++) {
                const char* pa = (const char*)A32 + gAo32[q] + koff32;
                aReg[b][q][0] = __ldg((const float4*)pa);
                aReg[b][q][1] = __ldg((const float4*)(pa + 16));
                CP_ASYNC(slot + SEC_B + sOff[q], (const char*)W + gBo[q] + koff);
            }
        }
        CP_COMMIT();
    };

    prefetch(0);
    prefetch(1);

    #pragma unroll 1
    for (int it = 0; it < NITER; it++) {
        CP_WAIT1();                       // W of stage `it` landed
        // convert + store A of stage `it` (regs loaded 2 stages ago)
        {
            const int b = it & 1;
            char* base = sm + (it % 3) * STAGE_B;
            #pragma unroll
            for (int q = 0; q < 4; q++) {
                const float4 f0 = aReg[b][q][0], f1 = aReg[b][q][1];
                uint4 h;
                h.x = pack_h2(f0.x, f0.y);
                h.y = pack_h2(f0.z, f0.w);
                h.z = pack_h2(f1.x, f1.y);
                h.w = pack_h2(f1.z, f1.w);
                *(uint4*)(base + sOff[q]) = h;
            }
        }
        __syncthreads();                  // A visible; slot (it+2)%3 free
        prefetch(it + 2);

        const uint32_t slot = sb + (uint32_t)(it % 3) * STAGE_B;
        #pragma unroll
        for (int ks = 0; ks < 4; ks++) {
            uint32_t a[4][4], w[2][4];
            #pragma unroll
            for (int mt = 0; mt < 4; mt++) {
                const uint32_t ro = (uint32_t)rA[mt] * 128 +
                    (uint32_t)((((ks * 2 + cA) ^ (rA[mt] & 7))) << 4);
                ldsm4(a[mt], slot + ro);
            }
            #pragma unroll
            for (int p = 0; p < 2; p++) {
                const uint32_t ro = (uint32_t)nB[p] * 128 +
                    (uint32_t)((((ks * 2 + cB) ^ (nB[p] & 7))) << 4);
                ldsm4(w[p], slot + SEC_B + ro);
            }
            #pragma unroll
            for (int mt = 0; mt < 4; mt++) {
                #pragma unroll
                for (int nt = 0; nt < 4; nt++) {
                    mma16816(acc[mt * 4 + nt], a[mt],
                             w[nt >> 1][(nt & 1) * 2], w[nt >> 1][(nt & 1) * 2 + 1]);
                }
            }
        }
    }

    #pragma unroll
    for (int mt = 0; mt < 4; mt++) {
        #pragma unroll
        for (int nt = 0; nt < 4; nt++) {
            const float* d = acc[mt * 4 + nt];
            const int row = m0 + wm * 64 + mt * 16 + gid;
            const int col = n0 + wn * 32 + nt * 8 + qid * 2;
            const float b0 = bcol[nt * 2], b1 = bcol[nt * 2 + 1];
            *(__half2*)(Vout + (size_t)row * CODE + col) =
                __halves2half2(__float2half_rn(d[0] + b0), __float2half_rn(d[1] + b1));
            *(__half2*)(Vout + (size_t)(row + 8) * CODE + col) =
                __halves2half2(__float2half_rn(d[2] + b0), __float2half_rn(d[3] + b1));
        }
    }
}

// ---------------- Householder: z -= 2 v (v.z)/(v.v), one warp per row ----------------
__global__ void __launch_bounds__(256)
hh_kernel(const __half* __restrict__ V,
          const float* __restrict__ z_in, float* __restrict__ z_out)
{
    const int lane = threadIdx.x & 31, warp = threadIdx.x >> 5;
    const size_t row = (size_t)blockIdx.x * 8 + warp;
    const __half* vp = V + row * CODE;
    const float* zi = z_in + row * CODE;

    float v[16], z[16];
    float vz = 0.f, vv = 0.f;
    #pragma unroll
    for (int ch = 0; ch < 4; ch++) {
        const int c = ch * 128 + lane * 4;
        uint2 hp = *(const uint2*)(vp + c);
        float4 zt = *(const float4*)(zi + c);
        float2 h0 = __half22float2(*(const __half2*)&hp.x);
        float2 h1 = __half22float2(*(const __half2*)&hp.y);
        v[ch*4+0] = h0.x; v[ch*4+1] = h0.y; v[ch*4+2] = h1.x; v[ch*4+3] = h1.y;
        z[ch*4+0] = zt.x; z[ch*4+1] = zt.y; z[ch*4+2] = zt.z; z[ch*4+3] = zt.w;
        #pragma unroll
        for (int j = 0; j < 4; j++) {
            vz += v[ch*4+j] * z[ch*4+j];
            vv += v[ch*4+j] * v[ch*4+j];
        }
    }
    #pragma unroll
    for (int o = 16; o; o >>= 1) {
        vz += __shfl_xor_sync(0xffffffffu, vz, o);
        vv += __shfl_xor_sync(0xffffffffu, vv, o);
    }
    const float s = 2.f * vz / vv;
    float* zo = z_out + row * CODE;
    #pragma unroll
    for (int ch = 0; ch < 4; ch++) {
        const int c = ch * 128 + lane * 4;
        float4 o;
        o.x = z[ch*4+0] - s * v[ch*4+0];
        o.y = z[ch*4+1] - s * v[ch*4+1];
        o.z = z[ch*4+2] - s * v[ch*4+2];
        o.w = z[ch*4+3] - s * v[ch*4+3];
        *(float4*)(zo + c) = o;
    }
}

// ---------------- stream/event context (load time; no device mem) ----------------
struct HHCtx {
    cudaStream_t sg[NCHAIN] = {}, sh[NCHAIN] = {};
    cudaEvent_t fork = nullptr, evW = nullptr;
    cudaEvent_t evG[NCHAIN][7] = {};
    cudaEvent_t evH[NCHAIN] = {};
    bool ok = false;
    HHCtx() {
        for (int c = 0; c < NCHAIN; c++) {
            if (cudaStreamCreateWithFlags(&sg[c], cudaStreamNonBlocking) != cudaSuccess) return;
            if (cudaStreamCreateWithFlags(&sh[c], cudaStreamNonBlocking) != cudaSuccess) return;
        }
        if (cudaEventCreateWithFlags(&fork, cudaEventDisableTiming) != cudaSuccess) return;
        if (cudaEventCreateWithFlags(&evW,  cudaEventDisableTiming) != cudaSuccess) return;
        for (int c = 0; c < NCHAIN; c++) {
            for (int l = 0; l < 7; l++)
                if (cudaEventCreateWithFlags(&evG[c][l], cudaEventDisableTiming) != cudaSuccess) return;
            if (cudaEventCreateWithFlags(&evH[c], cudaEventDisableTiming) != cudaSuccess) return;
        }
        ok = true;
    }
};
static HHCtx g_ctx;

// ---------------- host launch ----------------
extern "C" void kernel_launch(void* const* d_in, const int* in_sizes, int n_in,
                              void* d_out, int out_size)
{
    (void)in_sizes; (void)n_in; (void)out_size;
    const float* hidden = (const float*)d_in[0];
    const float* zs     = (const float*)d_in[1];
    const float* W0     = (const float*)d_in[2];
    const float* b0     = (const float*)d_in[3];
    const float* Ws     = (const float*)d_in[4];
    const float* bs     = (const float*)d_in[5];
    float* out = (float*)d_out;

    void *pW, *pV;
    cudaGetSymbolAddress(&pW, g_W);
    cudaGetSymbolAddress(&pV, g_V);
    __half* Wf = (__half*)pW;
    __half* Vb[3];
    Vb[0] = (__half*)pV;
    Vb[1] = Vb[0] + (size_t)BATCH * CODE;
    Vb[2] = Vb[1] + (size_t)BATCH * CODE;

    cudaFuncSetAttribute(gemm_l0,          cudaFuncAttributeMaxDynamicSharedMemorySize, GSMEM);
    cudaFuncSetAttribute(gemm_layer<CODE>, cudaFuncAttributeMaxDynamicSharedMemorySize, GSMEM);

    const int nW0 = CODE * HID, nWs = 6 * CODE * CODE;
    const dim3 ggrid(CROWS / 128, CODE / 128);    // 32 x 4 per chain
    const int hgrid = CROWS / 8;                  // 512 per chain

    if (!g_ctx.ok) {
        // fallback: fully serial on the capture stream (correct, slower)
        cvt_h<<<(nW0/4 + 255)/256, 256>>>((const float4*)W0, (__half2*)Wf, nW0/4);
        cvt_h<<<(nWs/4 + 255)/256, 256>>>((const float4*)Ws, (__half2*)(Wf + nW0), nWs/4);
        for (int c = 0; c < NCHAIN; c++) {
            const size_t vo = (size_t)c * CROWS * CODE;
            const size_t zo = (size_t)c * CROWS * CODE;
            gemm_l0<<<ggrid, 256, GSMEM>>>(hidden + (size_t)c * CROWS * HID, Wf, b0, Vb[0] + vo);
            hh_kernel<<<hgrid, 256>>>(Vb[0] + vo, zs + zo, out + zo);
            for (int l = 1; l <= 6; l++) {
                gemm_layer<CODE><<<ggrid, 256, GSMEM>>>(Vb[(l-1)%3] + vo,
                    Wf + nW0 + (size_t)(l-1)*CODE*CODE, bs + (l-1)*CODE, Vb[l%3] + vo);
                hh_kernel<<<hgrid, 256>>>(Vb[l%3] + vo, out + zo, out + zo);
            }
        }
        return;
    }

    // fork all streams off the capture stream
    cudaEventRecord(g_ctx.fork, 0);
    for (int c = 0; c < NCHAIN; c++) {
        cudaStreamWaitEvent(g_ctx.sg[c], g_ctx.fork, 0);
        cudaStreamWaitEvent(g_ctx.sh[c], g_ctx.fork, 0);
    }

    // weight converts on sg[0]; other chains wait on evW (R13 structure)
    cvt_h<<<(nW0/4 + 255)/256, 256, 0, g_ctx.sg[0]>>>((const float4*)W0, (__half2*)Wf, nW0/4);
    cvt_h<<<(nWs/4 + 255)/256, 256, 0, g_ctx.sg[0]>>>((const float4*)Ws, (__half2*)(Wf + nW0), nWs/4);
    cudaEventRecord(g_ctx.evW, g_ctx.sg[0]);
    for (int c = 1; c < NCHAIN; c++)
        cudaStreamWaitEvent(g_ctx.sg[c], g_ctx.evW, 0);

    // layer-major launch order across chains (R13 winner schedule);
    // layer 0 reads fp32 hidden directly (conversion fused)
    for (int l = 0; l < 7; l++) {
        for (int c = 0; c < NCHAIN; c++) {
            const size_t vo = (size_t)c * CROWS * CODE;
            const size_t zo = (size_t)c * CROWS * CODE;
            if (l == 0) {
                gemm_l0<<<ggrid, 256, GSMEM, g_ctx.sg[c]>>>(
                    hidden + (size_t)c * CROWS * HID, Wf, b0, Vb[0] + vo);
            } else {
                gemm_layer<CODE><<<ggrid, 256, GSMEM, g_ctx.sg[c]>>>(
                    Vb[(l-1)%3] + vo, Wf + nW0 + (size_t)(l-1)*CODE*CODE,
                    bs + (l-1)*CODE, Vb[l%3] + vo);
            }
            cudaEventRecord(g_ctx.evG[c][l], g_ctx.sg[c]);
            cudaStreamWaitEvent(g_ctx.sh[c], g_ctx.evG[c][l], 0);
            hh_kernel<<<hgrid, 256, 0, g_ctx.sh[c]>>>(
                Vb[l%3] + vo, (l == 0) ? zs + zo : out + zo, out + zo);
        }
    }

    // join: capture stream waits for every chain's hh tail
    for (int c = 0; c < NCHAIN; c++) {
        cudaEventRecord(g_ctx.evH[c], g_ctx.sh[c]);
        cudaStreamWaitEvent(0, g_ctx.evH[c], 0);
    }
}

// round 17
// speedup vs baseline: 1.2196x; 1.2196x over previous
#include <cuda_runtime.h>
#include <cuda_fp16.h>
#include <cstdint>

#define BATCH 16384
#define CODE  512
#define HID   1024
#define NCHAIN 4
#define CROWS (BATCH / NCHAIN)        // 4096 rows per chain

// ---------------- static device scratch ----------------
__device__ __half g_W[CODE*HID + 6*CODE*CODE];
__device__ __half g_H[BATCH*HID];
__device__ __half g_V[3][BATCH*CODE];    // 3-buffer rotation (no WAR race)

// ---------------- helpers ----------------
__device__ __forceinline__ uint32_t smem_u32(const void* p) {
    uint32_t a;
    asm("{ .reg .u64 t; cvta.to.shared.u64 t, %1; cvt.u32.u64 %0, t; }" : "=r"(a) : "l"(p));
    return a;
}
__device__ __forceinline__ void ldsm4(uint32_t* r, uint32_t a) {
    asm volatile("ldmatrix.sync.aligned.m8n8.x4.shared.b16 {%0,%1,%2,%3}, [%4];"
        : "=r"(r[0]), "=r"(r[1]), "=r"(r[2]), "=r"(r[3]) : "r"(a));
}
__device__ __forceinline__ void mma16816(float* d, const uint32_t* a, uint32_t b0, uint32_t b1) {
    asm volatile("mma.sync.aligned.m16n8k16.row.col.f32.f16.f16.f32 "
        "{%0,%1,%2,%3},{%4,%5,%6,%7},{%8,%9},{%0,%1,%2,%3};"
        : "+f"(d[0]), "+f"(d[1]), "+f"(d[2]), "+f"(d[3])
        : "r"(a[0]), "r"(a[1]), "r"(a[2]), "r"(a[3]), "r"(b0), "r"(b1));
}
#define CP_ASYNC(s, g) asm volatile("cp.async.cg.shared.global [%0], [%1], 16;" :: "r"(s), "l"(g))
#define CP_COMMIT()    asm volatile("cp.async.commit_group;")
#define CP_WAIT1()     asm volatile("cp.async.wait_group 1;")

// ---------------- converter: fp32 -> fp16 ----------------
__global__ void cvt_h(const float4* __restrict__ src, __half2* __restrict__ w, int n4) {
    int i = blockIdx.x * blockDim.x + threadIdx.x;
    if (i >= n4) return;
    float4 v = src[i];
    w[2*i]   = __halves2half2(__float2half_rn(v.x), __float2half_rn(v.y));
    w[2*i+1] = __halves2half2(__float2half_rn(v.z), __float2half_rn(v.w));
}

// ---------------- GEMM: V = A @ W^T + bias, fp16 single-pass ----------------
// CTA tile 128x128, 8 warps of 64x32, k-chunk 64, 3-stage cp.async pipeline,
// 2 CTAs/SM. Stage = A(16K)|W(16K), SW128 swizzle. (R10/R13 winner, unchanged.)
#define SEC_B    16384
#define STAGE_B  (2 * SEC_B)           // 32768
#define GSMEM    (3 * STAGE_B)         // 98304

template<int K>
__global__ void __launch_bounds__(256, 2)
gemm_layer(const __half* __restrict__ A, const __half* __restrict__ W,
           const float* __restrict__ bias, __half* __restrict__ Vout)
{
    extern __shared__ char sm[];
    const uint32_t sb = smem_u32(sm);
    const int tid = threadIdx.x, lane = tid & 31, wid = tid >> 5;
    const int wm = wid & 1, wn = wid >> 1;            // 2 x 4 warp grid
    const int m0 = blockIdx.x * 128, n0 = blockIdx.y * 128;
    constexpr int NITER = K / 64;

    const int lrow = tid >> 3, lc = tid & 7;
    uint32_t sOff[4], gAo[4], gBo[4];
    #pragma unroll
    for (int q = 0; q < 4; q++) {
        int row = lrow + q * 32;
        sOff[q] = (uint32_t)row * 128 + (uint32_t)((lc ^ (row & 7)) << 4);
        gAo[q] = (uint32_t)(m0 + row) * (K * 2) + lc * 16;
        gBo[q] = (uint32_t)(n0 + row) * (K * 2) + lc * 16;
    }

    int rA[4];
    #pragma unroll
    for (int mt = 0; mt < 4; mt++) rA[mt] = wm * 64 + mt * 16 + (lane & 15);
    const int cA = lane >> 4;
    int nB[2];
    #pragma unroll
    for (int p = 0; p < 2; p++) nB[p] = wn * 32 + p * 16 + (lane & 7) + ((lane >> 4) << 3);
    const int cB = (lane >> 3) & 1;

    const int gid = lane >> 2, qid = lane & 3;
    float bcol[8];
    #pragma unroll
    for (int nt = 0; nt < 4; nt++) {
        const int col = n0 + wn * 32 + nt * 8 + qid * 2;
        bcol[nt * 2]     = __ldg(bias + col);
        bcol[nt * 2 + 1] = __ldg(bias + col + 1);
    }

    float acc[16][4] = {};

    auto prefetch = [&](int it) {
        if (it < NITER) {
            const uint32_t slot = sb + (uint32_t)(it % 3) * STAGE_B;
            const uint32_t koff = (uint32_t)it * 128;
            #pragma unroll
            for (int q = 0; q < 4; q++) {
                CP_ASYNC(slot + sOff[q],         (const char*)A + gAo[q] + koff);
                CP_ASYNC(slot + SEC_B + sOff[q], (const char*)W + gBo[q] + koff);
            }
        }
        CP_COMMIT();
    };

    prefetch(0);
    prefetch(1);

    #pragma unroll 1
    for (int it = 0; it < NITER; it++) {
        CP_WAIT1();
        __syncthreads();
        prefetch(it + 2);

        const uint32_t slot = sb + (uint32_t)(it % 3) * STAGE_B;
        #pragma unroll
        for (int ks = 0; ks < 4; ks++) {
            uint32_t a[4][4], w[2][4];
            #pragma unroll
            for (int mt = 0; mt < 4; mt++) {
                const uint32_t ro = (uint32_t)rA[mt] * 128 +
                    (uint32_t)((((ks * 2 + cA) ^ (rA[mt] & 7))) << 4);
                ldsm4(a[mt], slot + ro);
            }
            #pragma unroll
            for (int p = 0; p < 2; p++) {
                const uint32_t ro = (uint32_t)nB[p] * 128 +
                    (uint32_t)((((ks * 2 + cB) ^ (nB[p] & 7))) << 4);
                ldsm4(w[p], slot + SEC_B + ro);
            }
            #pragma unroll
            for (int mt = 0; mt < 4; mt++) {
                #pragma unroll
                for (int nt = 0; nt < 4; nt++) {
                    mma16816(acc[mt * 4 + nt], a[mt],
                             w[nt >> 1][(nt & 1) * 2], w[nt >> 1][(nt & 1) * 2 + 1]);
                }
            }
        }
    }

    #pragma unroll
    for (int mt = 0; mt < 4; mt++) {
        #pragma unroll
        for (int nt = 0; nt < 4; nt++) {
            const float* d = acc[mt * 4 + nt];
            const int row = m0 + wm * 64 + mt * 16 + gid;
            const int col = n0 + wn * 32 + nt * 8 + qid * 2;
            const float b0 = bcol[nt * 2], b1 = bcol[nt * 2 + 1];
            *(__half2*)(Vout + (size_t)row * CODE + col) =
                __halves2half2(__float2half_rn(d[0] + b0), __float2half_rn(d[1] + b1));
            *(__half2*)(Vout + (size_t)(row + 8) * CODE + col) =
                __halves2half2(__float2half_rn(d[2] + b0), __float2half_rn(d[3] + b1));
        }
    }
}

// ---------------- Householder: z -= 2 v (v.z)/(v.v), one warp per row ----------------
__global__ void __launch_bounds__(256)
hh_kernel(const __half* __restrict__ V,
          const float* __restrict__ z_in, float* __restrict__ z_out)
{
    const int lane = threadIdx.x & 31, warp = threadIdx.x >> 5;
    const size_t row = (size_t)blockIdx.x * 8 + warp;
    const __half* vp = V + row * CODE;
    const float* zi = z_in + row * CODE;

    float v[16], z[16];
    float vz = 0.f, vv = 0.f;
    #pragma unroll
    for (int ch = 0; ch < 4; ch++) {
        const int c = ch * 128 + lane * 4;
        uint2 hp = *(const uint2*)(vp + c);
        float4 zt = *(const float4*)(zi + c);
        float2 h0 = __half22float2(*(const __half2*)&hp.x);
        float2 h1 = __half22float2(*(const __half2*)&hp.y);
        v[ch*4+0] = h0.x; v[ch*4+1] = h0.y; v[ch*4+2] = h1.x; v[ch*4+3] = h1.y;
        z[ch*4+0] = zt.x; z[ch*4+1] = zt.y; z[ch*4+2] = zt.z; z[ch*4+3] = zt.w;
        #pragma unroll
        for (int j = 0; j < 4; j++) {
            vz += v[ch*4+j] * z[ch*4+j];
            vv += v[ch*4+j] * v[ch*4+j];
        }
    }
    #pragma unroll
    for (int o = 16; o; o >>= 1) {
        vz += __shfl_xor_sync(0xffffffffu, vz, o);
        vv += __shfl_xor_sync(0xffffffffu, vv, o);
    }
    const float s = 2.f * vz / vv;
    float* zo = z_out + row * CODE;
    #pragma unroll
    for (int ch = 0; ch < 4; ch++) {
        const int c = ch * 128 + lane * 4;
        float4 o;
        o.x = z[ch*4+0] - s * v[ch*4+0];
        o.y = z[ch*4+1] - s * v[ch*4+1];
        o.z = z[ch*4+2] - s * v[ch*4+2];
        o.w = z[ch*4+3] - s * v[ch*4+3];
        *(float4*)(zo + c) = o;
    }
}

// ---------------- stream/event context (load time; no device mem) ----------------
struct HHCtx {
    cudaStream_t sg[NCHAIN] = {}, sh[NCHAIN] = {};
    cudaEvent_t fork = nullptr, evW = nullptr;
    cudaEvent_t evG[NCHAIN][7] = {};
    cudaEvent_t evH[NCHAIN] = {};
    bool ok = false;
    HHCtx() {
        for (int c = 0; c < NCHAIN; c++) {
            if (cudaStreamCreateWithFlags(&sg[c], cudaStreamNonBlocking) != cudaSuccess) return;
            if (cudaStreamCreateWithFlags(&sh[c], cudaStreamNonBlocking) != cudaSuccess) return;
        }
        if (cudaEventCreateWithFlags(&fork, cudaEventDisableTiming) != cudaSuccess) return;
        if (cudaEventCreateWithFlags(&evW,  cudaEventDisableTiming) != cudaSuccess) return;
        for (int c = 0; c < NCHAIN; c++) {
            for (int l = 0; l < 7; l++)
                if (cudaEventCreateWithFlags(&evG[c][l], cudaEventDisableTiming) != cudaSuccess) return;
            if (cudaEventCreateWithFlags(&evH[c], cudaEventDisableTiming) != cudaSuccess) return;
        }
        ok = true;
    }
};
static HHCtx g_ctx;

// ---------------- host launch ----------------
extern "C" void kernel_launch(void* const* d_in, const int* in_sizes, int n_in,
                              void* d_out, int out_size)
{
    (void)in_sizes; (void)n_in; (void)out_size;
    const float* hidden = (const float*)d_in[0];
    const float* zs     = (const float*)d_in[1];
    const float* W0     = (const float*)d_in[2];
    const float* b0     = (const float*)d_in[3];
    const float* Ws     = (const float*)d_in[4];
    const float* bs     = (const float*)d_in[5];
    float* out = (float*)d_out;

    void *pW, *pH, *pV;
    cudaGetSymbolAddress(&pW, g_W);
    cudaGetSymbolAddress(&pH, g_H);
    cudaGetSymbolAddress(&pV, g_V);
    __half* Wf = (__half*)pW;
    __half* Hf = (__half*)pH;
    __half* Vb[3];
    Vb[0] = (__half*)pV;
    Vb[1] = Vb[0] + (size_t)BATCH * CODE;
    Vb[2] = Vb[1] + (size_t)BATCH * CODE;

    cudaFuncSetAttribute(gemm_layer<HID>,  cudaFuncAttributeMaxDynamicSharedMemorySize, GSMEM);
    cudaFuncSetAttribute(gemm_layer<CODE>, cudaFuncAttributeMaxDynamicSharedMemorySize, GSMEM);

    const int nW0 = CODE * HID, nWs = 6 * CODE * CODE;
    const int nHq = CROWS * HID;                  // per-chain hidden elements
    const dim3 ggrid(CROWS / 128, CODE / 128);    // 32 x 4 per chain
    const int hgrid = CROWS / 8;                  // 512 per chain

    if (!g_ctx.ok) {
        // fallback: fully serial on the capture stream (correct, slower)
        cvt_h<<<(nW0/4 + 255)/256, 256>>>((const float4*)W0, (__half2*)Wf, nW0/4);
        cvt_h<<<(nWs/4 + 255)/256, 256>>>((const float4*)Ws, (__half2*)(Wf + nW0), nWs/4);
        cvt_h<<<(BATCH*HID/4 + 255)/256, 256>>>((const float4*)hidden, (__half2*)Hf, BATCH*HID/4);
        for (int c = 0; c < NCHAIN; c++) {
            const size_t ho = (size_t)c * CROWS * HID, vo = (size_t)c * CROWS * CODE;
            const size_t zo = (size_t)c * CROWS * CODE;
            gemm_layer<HID><<<ggrid, 256, GSMEM>>>(Hf + ho, Wf, b0, Vb[0] + vo);
            hh_kernel<<<hgrid, 256>>>(Vb[0] + vo, zs + zo, out + zo);
            for (int l = 1; l <= 6; l++) {
                gemm_layer<CODE><<<ggrid, 256, GSMEM>>>(Vb[(l-1)%3] + vo,
                    Wf + nW0 + (size_t)(l-1)*CODE*CODE, bs + (l-1)*CODE, Vb[l%3] + vo);
                hh_kernel<<<hgrid, 256>>>(Vb[l%3] + vo, out + zo, out + zo);
            }
        }
        return;
    }

    // fork all streams off the capture stream
    cudaEventRecord(g_ctx.fork, 0);
    for (int c = 0; c < NCHAIN; c++) {
        cudaStreamWaitEvent(g_ctx.sg[c], g_ctx.fork, 0);
        cudaStreamWaitEvent(g_ctx.sh[c], g_ctx.fork, 0);
    }

    // per-chain hidden converts FIRST (no weight dependency) — they overlap
    // the weight converts below instead of waiting behind them.
    for (int c = 1; c < NCHAIN; c++) {
        cvt_h<<<(nHq/4 + 255)/256, 256, 0, g_ctx.sg[c]>>>(
            (const float4*)(hidden + (size_t)c * nHq), (__half2*)(Hf + (size_t)c * nHq), nHq/4);
    }

    // weight converts on sg[0]; chain 0's hidden convert follows them there
    cvt_h<<<(nW0/4 + 255)/256, 256, 0, g_ctx.sg[0]>>>((const float4*)W0, (__half2*)Wf, nW0/4);
    cvt_h<<<(nWs/4 + 255)/256, 256, 0, g_ctx.sg[0]>>>((const float4*)Ws, (__half2*)(Wf + nW0), nWs/4);
    cudaEventRecord(g_ctx.evW, g_ctx.sg[0]);
    cvt_h<<<(nHq/4 + 255)/256, 256, 0, g_ctx.sg[0]>>>(
        (const float4*)hidden, (__half2*)Hf, nHq/4);
    // chains 1..3: gate their GEMMs (not their cvt) on the weight converts
    for (int c = 1; c < NCHAIN; c++)
        cudaStreamWaitEvent(g_ctx.sg[c], g_ctx.evW, 0);

    // layer-major launch order across chains (R13 winner schedule)
    for (int l = 0; l < 7; l++) {
        for (int c = 0; c < NCHAIN; c++) {
            const size_t vo = (size_t)c * CROWS * CODE;
            const size_t zo = (size_t)c * CROWS * CODE;
            if (l == 0) {
                gemm_layer<HID><<<ggrid, 256, GSMEM, g_ctx.sg[c]>>>(
                    Hf + (size_t)c * nHq, Wf, b0, Vb[0] + vo);
            } else {
                gemm_layer<CODE><<<ggrid, 256, GSMEM, g_ctx.sg[c]>>>(
                    Vb[(l-1)%3] + vo, Wf + nW0 + (size_t)(l-1)*CODE*CODE,
                    bs + (l-1)*CODE, Vb[l%3] + vo);
            }
            cudaEventRecord(g_ctx.evG[c][l], g_ctx.sg[c]);
            cudaStreamWaitEvent(g_ctx.sh[c], g_ctx.evG[c][l], 0);
            hh_kernel<<<hgrid, 256, 0, g_ctx.sh[c]>>>(
                Vb[l%3] + vo, (l == 0) ? zs + zo : out + zo, out + zo);
        }
    }

    // join: capture stream waits for every chain's hh tail
    for (int c = 0; c < NCHAIN; c++) {
        cudaEventRecord(g_ctx.evH[c], g_ctx.sh[c]);
        cudaStreamWaitEvent(0, g_ctx.evH[c], 0);
    }
}